// round 1
// baseline (speedup 1.0000x reference)
#include <cuda_runtime.h>
#include <math.h>

#define NDIM 768
#define FDIM 128
#define HDIM 128
#define NN (NDIM*NDIM)
#define EUP ((NDIM*(NDIM-1))/2)   // 294528 upper-triangle edges per batch

// scratch (no cudaMalloc allowed)
__device__ float g_Xc[2*2*NDIM*64];   // [b][ch][i][d]
__device__ float g_P[2*2*NN];         // [b][ch][i][j]  (only i<j tiles valid)

// ---------------------------------------------------------------------------
// K1: Xc = Xskip + gate * (relu(X@W1+b1)@W2+b2), reshaped to [b][ch][i][d]
// grid: 192 blocks x 128 threads, 8 rows per block
// ---------------------------------------------------------------------------
__global__ __launch_bounds__(128) void k_prep(
    const float* __restrict__ X,
    const float* __restrict__ w1, const float* __restrict__ b1,
    const float* __restrict__ w2, const float* __restrict__ b2,
    const float* __restrict__ gate)
{
    __shared__ float xs[8][FDIM];
    __shared__ float hs[8][HDIM];
    const int t = threadIdx.x;
    const int row0 = blockIdx.x * 8;          // 0..1528, never straddles batch
    const float g = gate[0];

    #pragma unroll
    for (int r = 0; r < 8; r++) xs[r][t] = X[(row0 + r) * FDIM + t];
    __syncthreads();

    float acc[8];
    {
        const float bb = b1[t];
        #pragma unroll
        for (int r = 0; r < 8; r++) acc[r] = bb;
        for (int f = 0; f < FDIM; f++) {
            const float w = w1[f * HDIM + t];
            #pragma unroll
            for (int r = 0; r < 8; r++) acc[r] = fmaf(xs[r][f], w, acc[r]);
        }
    }
    #pragma unroll
    for (int r = 0; r < 8; r++) hs[r][t] = fmaxf(acc[r], 0.0f);
    __syncthreads();
    {
        const float bb = b2[t];
        #pragma unroll
        for (int r = 0; r < 8; r++) acc[r] = bb;
        for (int h = 0; h < HDIM; h++) {
            const float w = w2[h * HDIM + t];
            #pragma unroll
            for (int r = 0; r < 8; r++) acc[r] = fmaf(hs[r][h], w, acc[r]);
        }
    }
    const int b  = row0 / NDIM;
    const int ch = t & 1;
    const int d  = t >> 1;
    #pragma unroll
    for (int r = 0; r < 8; r++) {
        const int i = (row0 + r) % NDIM;
        g_Xc[((b * 2 + ch) * NDIM + i) * 64 + d] = xs[r][t] + g * acc[r];
    }
}

// ---------------------------------------------------------------------------
// K2: gram  P[bc][i][j] = sum_d Xc[bc][i][d]*Xc[bc][j][d]
// 64x64 tiles, upper triangle only (bi<=bj): 78 tiles x 4 (b,ch) matrices
// 256 threads, 4x4 micro-tile per thread, smem stored transposed [d][row]
// ---------------------------------------------------------------------------
__global__ __launch_bounds__(256) void k_gram()
{
    __shared__ float As[64][68];   // [d][row i]  (pad 68: float4-aligned)
    __shared__ float Bs[64][68];   // [d][row j]
    const int tid = threadIdx.x;
    const int bc  = blockIdx.y;    // b*2+ch

    // decode upper-triangle tile index -> (bi,bj), 12 row-blocks
    int bi = 0, rem = blockIdx.x;
    while (rem >= 12 - bi) { rem -= 12 - bi; bi++; }
    const int bj = bi + rem;

    const float* Xbase = g_Xc + (size_t)bc * NDIM * 64;
    for (int idx = tid; idx < 4096; idx += 256) {
        const int r = idx >> 6, d = idx & 63;
        As[d][r] = Xbase[(bi * 64 + r) * 64 + d];
        Bs[d][r] = Xbase[(bj * 64 + r) * 64 + d];
    }
    __syncthreads();

    const int tx = tid & 15, ty = tid >> 4;
    float c[4][4];
    #pragma unroll
    for (int a = 0; a < 4; a++)
        #pragma unroll
        for (int bq = 0; bq < 4; bq++) c[a][bq] = 0.0f;

    #pragma unroll 8
    for (int d = 0; d < 64; d++) {
        const float4 av = *(const float4*)&As[d][ty * 4];
        const float4 bv = *(const float4*)&Bs[d][tx * 4];
        const float aa[4] = {av.x, av.y, av.z, av.w};
        const float bb[4] = {bv.x, bv.y, bv.z, bv.w};
        #pragma unroll
        for (int a = 0; a < 4; a++)
            #pragma unroll
            for (int bq = 0; bq < 4; bq++)
                c[a][bq] = fmaf(aa[a], bb[bq], c[a][bq]);
    }

    float* Pp = g_P + (size_t)bc * NN;
    const int i0 = bi * 64 + ty * 4;
    const int j0 = bj * 64 + tx * 4;
    #pragma unroll
    for (int a = 0; a < 4; a++) {
        float4 v = make_float4(c[a][0], c[a][1], c[a][2], c[a][3]);
        *(float4*)&Pp[(size_t)(i0 + a) * NDIM + j0] = v;
    }
}

// ---------------------------------------------------------------------------
// K3: per-edge score MLP + gumbel argmax decision, symmetric scatter + diag=0
// linearized upper-triangle edges, 8 per thread (perfect load balance)
// ---------------------------------------------------------------------------
__device__ __forceinline__ long cum_edges(int i) {
    return (long)i * (2 * NDIM - 1 - i) / 2;   // edges before row i
}

__global__ __launch_bounds__(256) void k_mlp(
    const float* __restrict__ sw1, const float* __restrict__ sb1,
    const float* __restrict__ sw2, const float* __restrict__ sb2,
    const float* __restrict__ gumbel, float* __restrict__ out)
{
    __shared__ float wa[HDIM], wb[HDIM], wc[HDIM], wdv[HDIM];
    const int t = threadIdx.x;
    if (t < HDIM) {
        wa[t]  = sw1[t];
        wb[t]  = sw1[HDIM + t];
        wc[t]  = sb1[t];
        wdv[t] = sw2[t * 2 + 1] - sw2[t * 2];
    }
    __syncthreads();
    const float bd = sb2[1] - sb2[0];

    const long gt = (long)blockIdx.x * 256 + t;

    // diagonal zeros (first 1536 threads, which also own valid edges)
    if (gt < 2 * NDIM) {
        const int b = (int)(gt / NDIM), i = (int)(gt % NDIM);
        out[(size_t)b * NN + (size_t)i * (NDIM + 1)] = 0.0f;
    }

    const long e0 = gt * 8;
    if (e0 >= 2L * EUP) return;
    const int b = (e0 >= EUP);            // EUP divisible by 8 -> no straddle
    long e = e0 - (long)b * EUP;

    // invert cum_edges via sqrt, then fix up
    const double dn = 2.0 * NDIM - 1.0;
    int i = (int)((dn - sqrt(dn * dn - 8.0 * (double)e)) * 0.5);
    if (i < 0) i = 0;
    while (cum_edges(i + 1) <= e) i++;
    while (cum_edges(i) > e) i--;
    int j = i + 1 + (int)(e - cum_edges(i));

    const float* P0 = g_P + (size_t)(b * 2 + 0) * NN;
    const float* P1 = g_P + (size_t)(b * 2 + 1) * NN;

    float p0[8], p1[8];
    int ii[8], jj[8];
    {
        int ci = i, cj = j;
        #pragma unroll
        for (int k = 0; k < 8; k++) {
            ii[k] = ci; jj[k] = cj;
            const size_t off = (size_t)ci * NDIM + cj;
            p0[k] = P0[off];
            p1[k] = P1[off];
            if (++cj == NDIM) { ci++; cj = ci + 1; }
        }
    }

    float acc[8];
    #pragma unroll
    for (int k = 0; k < 8; k++) acc[k] = 0.0f;

    #pragma unroll 4
    for (int h = 0; h < HDIM; h++) {
        const float a = wa[h], bb = wb[h], c = wc[h], w = wdv[h];
        #pragma unroll
        for (int k = 0; k < 8; k++) {
            const float pre = fmaf(a, p0[k], fmaf(bb, p1[k], c));
            acc[k] = fmaf(w, fmaxf(pre, 0.0f), acc[k]);
        }
    }

    const float* G = gumbel + (size_t)b * NN * 2;
    float* O = out + (size_t)b * NN;
    #pragma unroll
    for (int k = 0; k < 8; k++) {
        const float2 g2 = *(const float2*)&G[((size_t)ii[k] * NDIM + jj[k]) * 2];
        // A = 1 iff s1 + g1 > s0 + g0  (tie -> argmax picks 0 -> A=0)
        const float v = ((acc[k] + bd) + (g2.y - g2.x) > 0.0f) ? 1.0f : 0.0f;
        O[(size_t)ii[k] * NDIM + jj[k]] = v;
        O[(size_t)jj[k] * NDIM + ii[k]] = v;
    }
}

// ---------------------------------------------------------------------------
extern "C" void kernel_launch(void* const* d_in, const int* in_sizes, int n_in,
                              void* d_out, int out_size)
{
    const float* X     = (const float*)d_in[0];
    const float* ef_w1 = (const float*)d_in[1];
    const float* ef_b1 = (const float*)d_in[2];
    const float* ef_w2 = (const float*)d_in[3];
    const float* ef_b2 = (const float*)d_in[4];
    const float* gate  = (const float*)d_in[5];
    const float* sm_w1 = (const float*)d_in[6];
    const float* sm_b1 = (const float*)d_in[7];
    const float* sm_w2 = (const float*)d_in[8];
    const float* sm_b2 = (const float*)d_in[9];
    const float* gumb  = (const float*)d_in[10];
    float* out = (float*)d_out;

    k_prep<<<192, 128>>>(X, ef_w1, ef_b1, ef_w2, ef_b2, gate);
    k_gram<<<dim3(78, 4), 256>>>();
    const int nthreads = (2 * EUP) / 8;               // 73632
    const int nblocks  = (nthreads + 255) / 256;      // 288
    k_mlp<<<nblocks, 256>>>(sm_w1, sm_b1, sm_w2, sm_b2, gumb, out);
}

// round 2
// speedup vs baseline: 1.0336x; 1.0336x over previous
#include <cuda_runtime.h>
#include <math.h>
#include <string.h>

#define NDIM 768
#define FDIM 128
#define HDIM 128
#define NN (NDIM*NDIM)
#define EUP ((NDIM*(NDIM-1))/2)   // 294528 upper-triangle edges per batch

// scratch (no cudaMalloc allowed)
__device__ float g_Xc[2*2*NDIM*64];   // [b][ch][i][d]
__device__ float g_P[2*2*NN];         // [b][ch][i][j]  (only i<j tiles valid)

// packed 2xfp32 FMA (sm_100+); bit-identical to two scalar fmaf (RN)
union F2U { float2 f; unsigned long long u; };
__device__ __forceinline__ float2 ffma2(float2 a, float2 b, float2 c) {
    F2U A, B, C, D;
    A.f = a; B.f = b; C.f = c;
    asm("fma.rn.f32x2 %0, %1, %2, %3;" : "=l"(D.u) : "l"(A.u), "l"(B.u), "l"(C.u));
    return D.f;
}

// ---------------------------------------------------------------------------
// K1: Xc = Xskip + gate * (relu(X@W1+b1)@W2+b2), reshaped to [b][ch][i][d]
// 384 blocks x 128 threads, 4 rows per block (occupancy fix vs R1)
// ---------------------------------------------------------------------------
__global__ __launch_bounds__(128) void k_prep(
    const float* __restrict__ X,
    const float* __restrict__ w1, const float* __restrict__ b1,
    const float* __restrict__ w2, const float* __restrict__ b2,
    const float* __restrict__ gate)
{
    __shared__ float xs[4][FDIM];
    __shared__ float hs[4][HDIM];
    const int t = threadIdx.x;
    const int row0 = blockIdx.x * 4;          // never straddles batch
    const float g = gate[0];

    #pragma unroll
    for (int r = 0; r < 4; r++) xs[r][t] = X[(size_t)(row0 + r) * FDIM + t];
    __syncthreads();

    float acc[4];
    {
        const float bb = b1[t];
        #pragma unroll
        for (int r = 0; r < 4; r++) acc[r] = bb;
        #pragma unroll 8
        for (int f = 0; f < FDIM; f++) {
            const float w = w1[f * HDIM + t];
            #pragma unroll
            for (int r = 0; r < 4; r++) acc[r] = fmaf(xs[r][f], w, acc[r]);
        }
    }
    #pragma unroll
    for (int r = 0; r < 4; r++) hs[r][t] = fmaxf(acc[r], 0.0f);
    __syncthreads();
    {
        const float bb = b2[t];
        #pragma unroll
        for (int r = 0; r < 4; r++) acc[r] = bb;
        #pragma unroll 8
        for (int h = 0; h < HDIM; h++) {
            const float w = w2[h * HDIM + t];
            #pragma unroll
            for (int r = 0; r < 4; r++) acc[r] = fmaf(hs[r][h], w, acc[r]);
        }
    }
    const int b  = row0 / NDIM;
    const int ch = t & 1;
    const int d  = t >> 1;
    #pragma unroll
    for (int r = 0; r < 4; r++) {
        const int i = (row0 + r) % NDIM;
        g_Xc[((b * 2 + ch) * NDIM + i) * 64 + d] = xs[r][t] + g * acc[r];
    }
}

// ---------------------------------------------------------------------------
// K2: gram  P[bc][i][j] = sum_d Xc[bc][i][d]*Xc[bc][j][d]
// 64x64 tiles, upper triangle only (bi<=bj): 78 tiles x 4 (b,ch) matrices
// ---------------------------------------------------------------------------
__global__ __launch_bounds__(256) void k_gram()
{
    __shared__ float As[64][68];   // [d][row i]
    __shared__ float Bs[64][68];   // [d][row j]
    const int tid = threadIdx.x;
    const int bc  = blockIdx.y;    // b*2+ch

    int bi = 0, rem = blockIdx.x;
    while (rem >= 12 - bi) { rem -= 12 - bi; bi++; }
    const int bj = bi + rem;

    const float* Xbase = g_Xc + (size_t)bc * NDIM * 64;
    for (int idx = tid; idx < 4096; idx += 256) {
        const int r = idx >> 6, d = idx & 63;
        As[d][r] = Xbase[(bi * 64 + r) * 64 + d];
        Bs[d][r] = Xbase[(bj * 64 + r) * 64 + d];
    }
    __syncthreads();

    const int tx = tid & 15, ty = tid >> 4;
    float c[4][4];
    #pragma unroll
    for (int a = 0; a < 4; a++)
        #pragma unroll
        for (int bq = 0; bq < 4; bq++) c[a][bq] = 0.0f;

    #pragma unroll 8
    for (int d = 0; d < 64; d++) {
        const float4 av = *(const float4*)&As[d][ty * 4];
        const float4 bv = *(const float4*)&Bs[d][tx * 4];
        const float aa[4] = {av.x, av.y, av.z, av.w};
        const float bb[4] = {bv.x, bv.y, bv.z, bv.w};
        #pragma unroll
        for (int a = 0; a < 4; a++)
            #pragma unroll
            for (int bq = 0; bq < 4; bq++)
                c[a][bq] = fmaf(aa[a], bb[bq], c[a][bq]);
    }

    float* Pp = g_P + (size_t)bc * NN;
    const int i0 = bi * 64 + ty * 4;
    const int j0 = bj * 64 + tx * 4;
    #pragma unroll
    for (int a = 0; a < 4; a++) {
        float4 v = make_float4(c[a][0], c[a][1], c[a][2], c[a][3]);
        *(float4*)&Pp[(size_t)(i0 + a) * NDIM + j0] = v;
    }
}

// ---------------------------------------------------------------------------
// K3: per-edge score MLP + gumbel argmax decision, f32x2-packed
// ---------------------------------------------------------------------------
__device__ __forceinline__ long cum_edges(int i) {
    return (long)i * (2 * NDIM - 1 - i) / 2;
}

__global__ __launch_bounds__(256) void k_mlp(
    const float* __restrict__ sw1, const float* __restrict__ sb1,
    const float* __restrict__ sw2, const float* __restrict__ sb2,
    const float* __restrict__ gumbel, float* __restrict__ out)
{
    // duplicated weights as float2 for packed FMA (one LDS.64 per use)
    __shared__ float2 wa2[HDIM], wb2[HDIM], wc2[HDIM], wd2[HDIM];
    const int t = threadIdx.x;
    if (t < HDIM) {
        const float a = sw1[t];
        const float bb = sw1[HDIM + t];
        const float c = sb1[t];
        const float w = sw2[t * 2 + 1] - sw2[t * 2];
        wa2[t] = make_float2(a, a);
        wb2[t] = make_float2(bb, bb);
        wc2[t] = make_float2(c, c);
        wd2[t] = make_float2(w, w);
    }
    __syncthreads();
    const float bd = sb2[1] - sb2[0];

    const long gt = (long)blockIdx.x * 256 + t;

    if (gt < 2 * NDIM) {
        const int b = (int)(gt / NDIM), i = (int)(gt % NDIM);
        out[(size_t)b * NN + (size_t)i * (NDIM + 1)] = 0.0f;
    }

    const long e0 = gt * 8;
    if (e0 >= 2L * EUP) return;
    const int b = (e0 >= EUP);            // EUP % 8 == 0 -> no straddle
    long e = e0 - (long)b * EUP;

    const double dn = 2.0 * NDIM - 1.0;
    int i = (int)((dn - sqrt(dn * dn - 8.0 * (double)e)) * 0.5);
    if (i < 0) i = 0;
    while (cum_edges(i + 1) <= e) i++;
    while (cum_edges(i) > e) i--;
    int j = i + 1 + (int)(e - cum_edges(i));

    const float* P0 = g_P + (size_t)(b * 2 + 0) * NN;
    const float* P1 = g_P + (size_t)(b * 2 + 1) * NN;

    float2 p02[4], p12[4];
    int ii[8], jj[8];
    {
        int ci = i, cj = j;
        float p0s[8], p1s[8];
        #pragma unroll
        for (int k = 0; k < 8; k++) {
            ii[k] = ci; jj[k] = cj;
            const size_t off = (size_t)ci * NDIM + cj;
            p0s[k] = P0[off];
            p1s[k] = P1[off];
            if (++cj == NDIM) { ci++; cj = ci + 1; }
        }
        #pragma unroll
        for (int kp = 0; kp < 4; kp++) {
            p02[kp] = make_float2(p0s[2 * kp], p0s[2 * kp + 1]);
            p12[kp] = make_float2(p1s[2 * kp], p1s[2 * kp + 1]);
        }
    }

    float2 acc2[4];
    #pragma unroll
    for (int kp = 0; kp < 4; kp++) acc2[kp] = make_float2(0.0f, 0.0f);

    #pragma unroll 4
    for (int h = 0; h < HDIM; h++) {
        const float2 a2 = wa2[h];
        const float2 b2 = wb2[h];
        const float2 c2 = wc2[h];
        const float2 w2 = wd2[h];
        #pragma unroll
        for (int kp = 0; kp < 4; kp++) {
            float2 pre = ffma2(a2, p02[kp], ffma2(b2, p12[kp], c2));
            pre.x = fmaxf(pre.x, 0.0f);
            pre.y = fmaxf(pre.y, 0.0f);
            acc2[kp] = ffma2(w2, pre, acc2[kp]);
        }
    }

    const float* G = gumbel + (size_t)b * NN * 2;
    float* O = out + (size_t)b * NN;
    #pragma unroll
    for (int kp = 0; kp < 4; kp++) {
        #pragma unroll
        for (int half = 0; half < 2; half++) {
            const int k = 2 * kp + half;
            const float accv = half ? acc2[kp].y : acc2[kp].x;
            const float2 g2 = *(const float2*)&G[((size_t)ii[k] * NDIM + jj[k]) * 2];
            const float v = ((accv + bd) + (g2.y - g2.x) > 0.0f) ? 1.0f : 0.0f;
            O[(size_t)ii[k] * NDIM + jj[k]] = v;
            O[(size_t)jj[k] * NDIM + ii[k]] = v;
        }
    }
}

// ---------------------------------------------------------------------------
extern "C" void kernel_launch(void* const* d_in, const int* in_sizes, int n_in,
                              void* d_out, int out_size)
{
    const float* X     = (const float*)d_in[0];
    const float* ef_w1 = (const float*)d_in[1];
    const float* ef_b1 = (const float*)d_in[2];
    const float* ef_w2 = (const float*)d_in[3];
    const float* ef_b2 = (const float*)d_in[4];
    const float* gate  = (const float*)d_in[5];
    const float* sm_w1 = (const float*)d_in[6];
    const float* sm_b1 = (const float*)d_in[7];
    const float* sm_w2 = (const float*)d_in[8];
    const float* sm_b2 = (const float*)d_in[9];
    const float* gumb  = (const float*)d_in[10];
    float* out = (float*)d_out;

    k_prep<<<384, 128>>>(X, ef_w1, ef_b1, ef_w2, ef_b2, gate);
    k_gram<<<dim3(78, 4), 256>>>();
    const int nthreads = (2 * EUP) / 8;               // 73632
    const int nblocks  = (nthreads + 255) / 256;      // 288
    k_mlp<<<nblocks, 256>>>(sm_w1, sm_b1, sm_w2, sm_b2, gumb, out);
}

// round 3
// speedup vs baseline: 1.1529x; 1.1154x over previous
#include <cuda_runtime.h>
#include <math.h>

#define NDIM 768
#define FDIM 128
#define HDIM 128
#define NN (NDIM*NDIM)
#define EUP ((NDIM*(NDIM-1))/2)   // 294528 upper-triangle edges per batch

// scratch (no cudaMalloc allowed)
__device__ float g_Xc[2*2*NDIM*64];   // [b][ch][i][d]
__device__ float g_P[2*2*NN];         // [b][ch][i][j]  (only i<j tiles valid)

// packed 2xfp32 FMA (sm_100+); bit-identical to two scalar fmaf (RN)
union F2U { float2 f; unsigned long long u; };
__device__ __forceinline__ float2 ffma2(float2 a, float2 b, float2 c) {
    F2U A, B, C, D;
    A.f = a; B.f = b; C.f = c;
    asm("fma.rn.f32x2 %0, %1, %2, %3;" : "=l"(D.u) : "l"(A.u), "l"(B.u), "l"(C.u));
    return D.f;
}

// ---------------------------------------------------------------------------
// K1: Xc = Xskip + gate * (relu(X@W1+b1)@W2+b2)
// 192 blocks x 128 threads, 8 rows/block.
// Weights double-buffered in REGISTERS (prefetch next 16 while computing 16)
// so the compute loop never waits on global latency. Rows packed 2-wide for
// fma.f32x2.
// ---------------------------------------------------------------------------
#define PR_ROWS 8
#define PR_CH   16   // f-chunk size (128/16 = 8 chunks per layer)

__global__ __launch_bounds__(128) void k_prep(
    const float* __restrict__ X,
    const float* __restrict__ w1, const float* __restrict__ b1,
    const float* __restrict__ w2, const float* __restrict__ b2,
    const float* __restrict__ gate)
{
    __shared__ float xs[FDIM][PR_ROWS];   // [f][r]  4KB
    __shared__ float hs[HDIM][PR_ROWS];   // [h][r]  4KB
    const int t = threadIdx.x;
    const int row0 = blockIdx.x * PR_ROWS;    // never straddles batch
    const float g = gate[0];

    #pragma unroll
    for (int r = 0; r < PR_ROWS; r++)
        xs[t][r] = X[(size_t)(row0 + r) * FDIM + t];
    __syncthreads();

    float2 acc[4];

    // ---------------- layer 1: hs = relu(X @ w1 + b1) ----------------
    {
        const float bb = b1[t];
        #pragma unroll
        for (int p = 0; p < 4; p++) acc[p] = make_float2(bb, bb);

        const float* wp = w1 + t;
        float wreg[2][PR_CH];
        #pragma unroll
        for (int u = 0; u < PR_CH; u++) wreg[0][u] = wp[u * HDIM];

        #pragma unroll
        for (int c = 0; c < FDIM / PR_CH; c++) {
            const int cur = c & 1;
            if (c < FDIM / PR_CH - 1) {
                #pragma unroll
                for (int u = 0; u < PR_CH; u++)
                    wreg[cur ^ 1][u] = wp[((c + 1) * PR_CH + u) * HDIM];
            }
            #pragma unroll
            for (int u = 0; u < PR_CH; u++) {
                const int f = c * PR_CH + u;
                const float w = wreg[cur][u];
                const float2 wv = make_float2(w, w);
                const float4 x03 = *(const float4*)&xs[f][0];
                const float4 x47 = *(const float4*)&xs[f][4];
                acc[0] = ffma2(make_float2(x03.x, x03.y), wv, acc[0]);
                acc[1] = ffma2(make_float2(x03.z, x03.w), wv, acc[1]);
                acc[2] = ffma2(make_float2(x47.x, x47.y), wv, acc[2]);
                acc[3] = ffma2(make_float2(x47.z, x47.w), wv, acc[3]);
            }
        }
    }
    #pragma unroll
    for (int p = 0; p < 4; p++) {
        hs[t][2 * p]     = fmaxf(acc[p].x, 0.0f);
        hs[t][2 * p + 1] = fmaxf(acc[p].y, 0.0f);
    }
    __syncthreads();

    // ---------------- layer 2: act = hs @ w2 + b2 ----------------
    {
        const float bb = b2[t];
        #pragma unroll
        for (int p = 0; p < 4; p++) acc[p] = make_float2(bb, bb);

        const float* wp = w2 + t;
        float wreg[2][PR_CH];
        #pragma unroll
        for (int u = 0; u < PR_CH; u++) wreg[0][u] = wp[u * HDIM];

        #pragma unroll
        for (int c = 0; c < HDIM / PR_CH; c++) {
            const int cur = c & 1;
            if (c < HDIM / PR_CH - 1) {
                #pragma unroll
                for (int u = 0; u < PR_CH; u++)
                    wreg[cur ^ 1][u] = wp[((c + 1) * PR_CH + u) * HDIM];
            }
            #pragma unroll
            for (int u = 0; u < PR_CH; u++) {
                const int h = c * PR_CH + u;
                const float w = wreg[cur][u];
                const float2 wv = make_float2(w, w);
                const float4 h03 = *(const float4*)&hs[h][0];
                const float4 h47 = *(const float4*)&hs[h][4];
                acc[0] = ffma2(make_float2(h03.x, h03.y), wv, acc[0]);
                acc[1] = ffma2(make_float2(h03.z, h03.w), wv, acc[1]);
                acc[2] = ffma2(make_float2(h47.x, h47.y), wv, acc[2]);
                acc[3] = ffma2(make_float2(h47.z, h47.w), wv, acc[3]);
            }
        }
    }

    // ---------------- output: Xc = Xskip + g * act ----------------
    const int b  = row0 / NDIM;
    const int ch = t & 1;
    const int d  = t >> 1;
    const int i0 = row0 % NDIM;
    float* dst = g_Xc + ((size_t)(b * 2 + ch) * NDIM + i0) * 64 + d;
    #pragma unroll
    for (int p = 0; p < 4; p++) {
        dst[(size_t)(2 * p)     * 64] = xs[t][2 * p]     + g * acc[p].x;
        dst[(size_t)(2 * p + 1) * 64] = xs[t][2 * p + 1] + g * acc[p].y;
    }
}

// ---------------------------------------------------------------------------
// K2: gram  P[bc][i][j] = sum_d Xc[bc][i][d]*Xc[bc][j][d]
// 64x64 tiles, upper triangle only; f32x2-packed along j
// ---------------------------------------------------------------------------
__global__ __launch_bounds__(256) void k_gram()
{
    __shared__ float As[64][68];   // [d][row i]
    __shared__ float Bs[64][68];   // [d][row j]
    const int tid = threadIdx.x;
    const int bc  = blockIdx.y;    // b*2+ch

    int bi = 0, rem = blockIdx.x;
    while (rem >= 12 - bi) { rem -= 12 - bi; bi++; }
    const int bj = bi + rem;

    const float* Xbase = g_Xc + (size_t)bc * NDIM * 64;
    for (int idx = tid; idx < 4096; idx += 256) {
        const int r = idx >> 6, d = idx & 63;
        As[d][r] = Xbase[(bi * 64 + r) * 64 + d];
        Bs[d][r] = Xbase[(bj * 64 + r) * 64 + d];
    }
    __syncthreads();

    const int tx = tid & 15, ty = tid >> 4;
    float2 c2[4][2];
    #pragma unroll
    for (int a = 0; a < 4; a++) {
        c2[a][0] = make_float2(0.0f, 0.0f);
        c2[a][1] = make_float2(0.0f, 0.0f);
    }

    #pragma unroll 8
    for (int d = 0; d < 64; d++) {
        const float4 av = *(const float4*)&As[d][ty * 4];
        const float4 bv = *(const float4*)&Bs[d][tx * 4];
        const float2 b01 = make_float2(bv.x, bv.y);
        const float2 b23 = make_float2(bv.z, bv.w);
        const float aa[4] = {av.x, av.y, av.z, av.w};
        #pragma unroll
        for (int a = 0; a < 4; a++) {
            const float2 a2 = make_float2(aa[a], aa[a]);
            c2[a][0] = ffma2(a2, b01, c2[a][0]);
            c2[a][1] = ffma2(a2, b23, c2[a][1]);
        }
    }

    float* Pp = g_P + (size_t)bc * NN;
    const int i0 = bi * 64 + ty * 4;
    const int j0 = bj * 64 + tx * 4;
    #pragma unroll
    for (int a = 0; a < 4; a++) {
        float4 v = make_float4(c2[a][0].x, c2[a][0].y, c2[a][1].x, c2[a][1].y);
        *(float4*)&Pp[(size_t)(i0 + a) * NDIM + j0] = v;
    }
}

// ---------------------------------------------------------------------------
// K3: per-edge score MLP + gumbel argmax decision, f32x2-packed
// ---------------------------------------------------------------------------
__device__ __forceinline__ long cum_edges(int i) {
    return (long)i * (2 * NDIM - 1 - i) / 2;
}

__global__ __launch_bounds__(256) void k_mlp(
    const float* __restrict__ sw1, const float* __restrict__ sb1,
    const float* __restrict__ sw2, const float* __restrict__ sb2,
    const float* __restrict__ gumbel, float* __restrict__ out)
{
    __shared__ float2 wa2[HDIM], wb2[HDIM], wc2[HDIM], wd2[HDIM];
    const int t = threadIdx.x;
    if (t < HDIM) {
        const float a = sw1[t];
        const float bb = sw1[HDIM + t];
        const float c = sb1[t];
        const float w = sw2[t * 2 + 1] - sw2[t * 2];
        wa2[t] = make_float2(a, a);
        wb2[t] = make_float2(bb, bb);
        wc2[t] = make_float2(c, c);
        wd2[t] = make_float2(w, w);
    }
    __syncthreads();
    const float bd = sb2[1] - sb2[0];

    const long gt = (long)blockIdx.x * 256 + t;

    if (gt < 2 * NDIM) {
        const int b = (int)(gt / NDIM), i = (int)(gt % NDIM);
        out[(size_t)b * NN + (size_t)i * (NDIM + 1)] = 0.0f;
    }

    const long e0 = gt * 8;
    if (e0 >= 2L * EUP) return;
    const int b = (e0 >= EUP);            // EUP % 8 == 0 -> no straddle
    long e = e0 - (long)b * EUP;

    const double dn = 2.0 * NDIM - 1.0;
    int i = (int)((dn - sqrt(dn * dn - 8.0 * (double)e)) * 0.5);
    if (i < 0) i = 0;
    while (cum_edges(i + 1) <= e) i++;
    while (cum_edges(i) > e) i--;
    int j = i + 1 + (int)(e - cum_edges(i));

    const float* P0 = g_P + (size_t)(b * 2 + 0) * NN;
    const float* P1 = g_P + (size_t)(b * 2 + 1) * NN;

    float2 p02[4], p12[4];
    int ii[8], jj[8];
    {
        int ci = i, cj = j;
        float p0s[8], p1s[8];
        #pragma unroll
        for (int k = 0; k < 8; k++) {
            ii[k] = ci; jj[k] = cj;
            const size_t off = (size_t)ci * NDIM + cj;
            p0s[k] = P0[off];
            p1s[k] = P1[off];
            if (++cj == NDIM) { ci++; cj = ci + 1; }
        }
        #pragma unroll
        for (int kp = 0; kp < 4; kp++) {
            p02[kp] = make_float2(p0s[2 * kp], p0s[2 * kp + 1]);
            p12[kp] = make_float2(p1s[2 * kp], p1s[2 * kp + 1]);
        }
    }

    float2 acc2[4];
    #pragma unroll
    for (int kp = 0; kp < 4; kp++) acc2[kp] = make_float2(0.0f, 0.0f);

    #pragma unroll 4
    for (int h = 0; h < HDIM; h++) {
        const float2 a2 = wa2[h];
        const float2 b2 = wb2[h];
        const float2 c2 = wc2[h];
        const float2 w2 = wd2[h];
        #pragma unroll
        for (int kp = 0; kp < 4; kp++) {
            float2 pre = ffma2(a2, p02[kp], ffma2(b2, p12[kp], c2));
            pre.x = fmaxf(pre.x, 0.0f);
            pre.y = fmaxf(pre.y, 0.0f);
            acc2[kp] = ffma2(w2, pre, acc2[kp]);
        }
    }

    const float* G = gumbel + (size_t)b * NN * 2;
    float* O = out + (size_t)b * NN;
    #pragma unroll
    for (int kp = 0; kp < 4; kp++) {
        #pragma unroll
        for (int half = 0; half < 2; half++) {
            const int k = 2 * kp + half;
            const float accv = half ? acc2[kp].y : acc2[kp].x;
            const float2 g2 = *(const float2*)&G[((size_t)ii[k] * NDIM + jj[k]) * 2];
            const float v = ((accv + bd) + (g2.y - g2.x) > 0.0f) ? 1.0f : 0.0f;
            O[(size_t)ii[k] * NDIM + jj[k]] = v;
            O[(size_t)jj[k] * NDIM + ii[k]] = v;
        }
    }
}

// ---------------------------------------------------------------------------
extern "C" void kernel_launch(void* const* d_in, const int* in_sizes, int n_in,
                              void* d_out, int out_size)
{
    const float* X     = (const float*)d_in[0];
    const float* ef_w1 = (const float*)d_in[1];
    const float* ef_b1 = (const float*)d_in[2];
    const float* ef_w2 = (const float*)d_in[3];
    const float* ef_b2 = (const float*)d_in[4];
    const float* gate  = (const float*)d_in[5];
    const float* sm_w1 = (const float*)d_in[6];
    const float* sm_b1 = (const float*)d_in[7];
    const float* sm_w2 = (const float*)d_in[8];
    const float* sm_b2 = (const float*)d_in[9];
    const float* gumb  = (const float*)d_in[10];
    float* out = (float*)d_out;

    k_prep<<<192, 128>>>(X, ef_w1, ef_b1, ef_w2, ef_b2, gate);
    k_gram<<<dim3(78, 4), 256>>>();
    const int nthreads = (2 * EUP) / 8;               // 73632
    const int nblocks  = (nthreads + 255) / 256;      // 288
    k_mlp<<<nblocks, 256>>>(sm_w1, sm_b1, sm_w2, sm_b2, gumb, out);
}